// round 16
// baseline (speedup 1.0000x reference)
#include <cuda_runtime.h>
#include <cstdint>
#include <math.h>

#define N_IMG   4
#define N_ANCH  76725
#define N_CLS   80
#define PRE     512
#define CAND_MAX 2048
#define MAXPC   100
#define MAXD    100
#define NLIST   (N_IMG * N_CLS)

// logit(0.91): s > 0.91 <=> x > 2.3136168
#define XTHR 2.3136168f

#define MAIN_SMEM 71872
#define MRG_SMEM 20800
#define MRG_THREADS 1024

// ---------------- scratch ----------------
__device__ unsigned long long g_cand[(size_t)NLIST * CAND_MAX];
__device__ uint32_t g_cnt[NLIST];                // zeroed at load; k_merge re-zeros each launch
__device__ float  g_cls_scores[NLIST * MAXPC];
__device__ float4 g_cls_boxes [NLIST * MAXPC];

// decode anchor a -> (cx, cy, aw, ah)
__device__ __forceinline__ void anchor_params(int a, float& cx, float& cy, float& aw, float& ah) {
    int off, fw, stride;
    if      (a < 57600) { off = 0;     fw = 80; stride = 8;   }
    else if (a < 72000) { off = 57600; fw = 40; stride = 16;  }
    else if (a < 75600) { off = 72000; fw = 20; stride = 32;  }
    else if (a < 76500) { off = 75600; fw = 10; stride = 64;  }
    else                { off = 76500; fw = 5;  stride = 128; }
    int rem  = a - off;
    int cell = rem / 9, k = rem - cell * 9;
    int iy = cell / fw, ix = cell - iy * fw;
    float sf    = (float)stride;
    float area  = 16.0f * sf * sf;
    float ratio = (k < 3) ? 0.5f : ((k < 6) ? 1.0f : 2.0f);
    int   si    = k % 3;
    float scale = (si == 0) ? 1.0f : ((si == 1) ? 1.2599210498948732f : 1.5874010519681994f);
    float hh = sqrtf(area / ratio);
    float ww = area / hh;
    cx = (ix + 0.5f) * sf;
    cy = (iy + 0.5f) * sf;
    aw = scale * ww;
    ah = scale * hh;
}

// ---------------- kernel 1: lean logit scan, single-ballot warp-aggregated push ----------------
#define PREP_THREADS 512
#define PREP_UNROLL 4
#define PREP_BUF 1024
__global__ __launch_bounds__(PREP_THREADS) void k_prep(const float* __restrict__ pred) {
    __shared__ unsigned long long skey[PREP_BUF];
    __shared__ uint32_t slist[PREP_BUF];
    __shared__ uint32_t scount[NLIST];
    __shared__ uint32_t sbase [NLIST];
    __shared__ uint32_t scursor[NLIST];
    __shared__ uint32_t snum;

    const int TOTV = N_IMG * N_ANCH * 21;
    const int PERIOD = N_ANCH * 21;
    const float4* __restrict__ p4 = (const float4*)pred;
    int tid = threadIdx.x;
    int lane = tid & 31;
    const uint32_t F = 0xFFFFFFFFu;

    if (tid == 0) snum = 0;
    for (int i = tid; i < NLIST; i += PREP_THREADS) { scount[i] = 0; scursor[i] = 0; }
    __syncthreads();

    int base = blockIdx.x * (PREP_THREADS * PREP_UNROLL) + tid;

    float4 v[PREP_UNROLL];
    #pragma unroll
    for (int i = 0; i < PREP_UNROLL; i++) {
        int g = base + i * PREP_THREADS;
        if (g < TOTV) v[i] = p4[g];
    }

    // q = g % 21, maintained incrementally (step 512 % 21 == 8)
    int q = base % 21;

    #pragma unroll
    for (int i = 0; i < PREP_UNROLL; i++) {
        int g = base + i * PREP_THREADS;
        bool inb = (g < TOTV);
        bool isLogit = inb && (q != 0);

        // per-thread 4-bit candidate mask
        uint32_t cmask = 0;
        if (isLogit) {
            cmask  = (v[i].x > XTHR) ? 1u : 0u;
            cmask |= (v[i].y > XTHR) ? 2u : 0u;
            cmask |= (v[i].z > XTHR) ? 4u : 0u;
            cmask |= (v[i].w > XTHR) ? 8u : 0u;
        }

        if (__ballot_sync(F, cmask != 0u)) {
            // ONE prefix-sum + ONE atomic for the whole warp
            uint32_t nc = (uint32_t)__popc(cmask);
            uint32_t incl = nc;
            #pragma unroll
            for (int d = 1; d < 32; d <<= 1) {
                uint32_t n = __shfl_up_sync(F, incl, d);
                if (lane >= d) incl += n;
            }
            uint32_t totw = __shfl_sync(F, incl, 31);
            uint32_t wbase = 0;
            if (lane == 31) wbase = atomicAdd(&snum, totw);
            wbase = __shfl_sync(F, wbase, 31);
            uint32_t my = wbase + incl - nc;

            if (cmask) {
                int img = g / PERIOD;
                int a   = (g - img * PERIOD) / 21;
                uint32_t listbase = (uint32_t)(img * N_CLS + 4 * q - 4);
                float xs[4] = {v[i].x, v[i].y, v[i].z, v[i].w};
                #pragma unroll
                for (int j = 0; j < 4; j++) {
                    if ((cmask >> j) & 1u) {
                        float s = __fdividef(1.0f, 1.0f + __expf(-xs[j]));
                        uint32_t mono = __float_as_uint(s) | 0x80000000u;
                        uint32_t list = listbase + j;
                        unsigned long long key =
                            ((unsigned long long)mono << 32) | (uint32_t)(~(uint32_t)a);
                        uint32_t idx = my++;
                        if (idx < PREP_BUF) {
                            skey[idx]  = key;
                            slist[idx] = list;
                        } else {
                            uint32_t p = atomicAdd(&g_cnt[list], 1u);
                            if (p < CAND_MAX) g_cand[(size_t)list * CAND_MAX + p] = key;
                        }
                    }
                }
            }
        }
        q += 8; if (q >= 21) q -= 21;
    }
    __syncthreads();

    int tot = (int)min(snum, (uint32_t)PREP_BUF);

    for (int i = tid; i < tot; i += PREP_THREADS)
        atomicAdd(&scount[slist[i]], 1u);
    __syncthreads();

    for (int l = tid; l < NLIST; l += PREP_THREADS)
        if (scount[l]) sbase[l] = atomicAdd(&g_cnt[l], scount[l]);
    __syncthreads();

    for (int i = tid; i < tot; i += PREP_THREADS) {
        uint32_t l = slist[i];
        uint32_t pos = sbase[l] + atomicAdd(&scursor[l], 1u);
        if (pos < CAND_MAX) g_cand[(size_t)l * CAND_MAX + pos] = skey[i];
    }
}

// suffix scan over 512 threads
__device__ __forceinline__ void suffix_scan_512(uint32_t v, uint32_t* sufp,
                                                uint32_t* wsum, uint32_t* wsuf, int tid) {
    int lane = tid & 31, wid = tid >> 5;
    uint32_t incl = v;
    #pragma unroll
    for (int d = 1; d < 32; d <<= 1) {
        uint32_t n = __shfl_down_sync(0xFFFFFFFFu, incl, d);
        if (lane + d < 32) incl += n;
    }
    if (lane == 0) wsum[wid] = incl;
    __syncthreads();
    if (tid < 16) {
        uint32_t x = wsum[tid];
        #pragma unroll
        for (int d = 1; d < 16; d <<= 1) {
            uint32_t n = __shfl_down_sync(0x0000FFFFu, x, d);
            if (tid + d < 16) x += n;
        }
        wsuf[tid] = x;
    }
    __syncthreads();
    uint32_t below = (wid < 15) ? wsuf[wid + 1] : 0u;
    sufp[tid] = incl + below;
    if (tid == 0) sufp[512] = 0;
    __syncthreads();
}

// suffix scan over 1024 threads (k_merge)
__device__ __forceinline__ void suffix_scan_1024(uint32_t v, uint32_t* sufp,
                                                 uint32_t* wsum, uint32_t* wsuf, int tid) {
    int lane = tid & 31, wid = tid >> 5;   // 32 warps
    uint32_t incl = v;
    #pragma unroll
    for (int d = 1; d < 32; d <<= 1) {
        uint32_t n = __shfl_down_sync(0xFFFFFFFFu, incl, d);
        if (lane + d < 32) incl += n;
    }
    if (lane == 0) wsum[wid] = incl;
    __syncthreads();
    if (tid < 32) {
        uint32_t x = wsum[tid];
        #pragma unroll
        for (int d = 1; d < 32; d <<= 1) {
            uint32_t n = __shfl_down_sync(0xFFFFFFFFu, x, d);
            if (tid + d < 32) x += n;
        }
        wsuf[tid] = x;
    }
    __syncthreads();
    uint32_t below = (wid < 31) ? wsuf[wid + 1] : 0u;
    sufp[tid] = incl + below;
    if (tid == 0) sufp[1024] = 0;
    __syncthreads();
}

__device__ __forceinline__ void agg_hist_add(uint32_t* hist, uint32_t bin, bool active) {
    uint32_t amask = __ballot_sync(0xFFFFFFFFu, active);
    if (!active) return;
    uint32_t peers  = __match_any_sync(amask, bin);
    int      leader = __ffs(peers) - 1;
    if ((threadIdx.x & 31) == leader) atomicAdd(&hist[bin], (uint32_t)__popc(peers));
}

// pair-indexed bitonic sort, NT threads
template<int NT>
__device__ __forceinline__ void bitonic_sort_t(unsigned long long* keys, int SORTN, int tid) {
    int npairs = SORTN >> 1;
    for (int k = 2; k <= SORTN; k <<= 1) {
        for (int j = k >> 1; j > 0; j >>= 1) {
            for (int p = tid; p < npairs; p += NT) {
                int i = ((p & ~(j - 1)) << 1) | (p & (j - 1));
                int l = i + j;
                unsigned long long x = keys[i], y = keys[l];
                bool up = ((i & k) == 0);
                if (up ? (x > y) : (x < y)) { keys[i] = y; keys[l] = x; }
            }
            __syncthreads();
        }
    }
}

// IoU bitmask tiles [t0,t1) striped over 16 warps; mask[row*16+J]
__device__ __forceinline__ void iou_tiles(const float4* sxy, const float* sar,
                                          uint32_t* mask, int t0, int t1,
                                          int w, int lane) {
    for (int t = t0 + w; t < t1; t += 16) {
        int J = 0;
        #pragma unroll
        for (int jj = 1; jj < 16; jj++) if ((jj * (jj + 1)) / 2 <= t) J = jj;
        int I = t - (J * (J + 1)) / 2;

        int col = 32 * J + lane;
        float4 me = sxy[col];
        float  aj = sar[col];
        bool diag = (I == J);

        #pragma unroll 4
        for (int r = 0; r < 32; r++) {
            int row = 32 * I + r;
            float4 bi = sxy[row];
            float lx = fmaxf(bi.x, me.x), ly = fmaxf(bi.y, me.y);
            float rx = fminf(bi.z, me.z), ry = fminf(bi.w, me.w);
            float ww = fmaxf(rx - lx, 0.0f), hh = fmaxf(ry - ly, 0.0f);
            float inter = ww * hh;
            float un = fmaxf(sar[row] + aj - inter, 1e-8f);
            bool bit = (inter > 0.5f * un) && (!diag || (lane > r));
            uint32_t bm = __ballot_sync(0xFFFFFFFFu, bit);
            if (lane == 0) mask[row * 16 + J] = bm;
        }
    }
}

// greedy over G groups; emits keepers; count in scal[0]
__device__ __forceinline__ void greedy_emit(const float* ssc, const float4* sxyw,
                                            const uint32_t* mask, uint32_t* scal,
                                            int G, int bid, int tid) {
    if (tid < 32) {
        const uint32_t F = 0xFFFFFFFFu;
        int l = tid;
        uint32_t validw = 0;
        if (l < G) {
            #pragma unroll
            for (int b = 0; b < 32; b++)
                validw |= (ssc[l * 32 + b] > 0.05f) ? (1u << b) : 0u;
        }
        uint32_t keepw = 0xFFFFFFFFu;
        #pragma unroll 1
        for (int g = 0; g < G; g++) {
            uint32_t vwg  = __shfl_sync(F, validw, g);
            uint32_t kloc = __shfl_sync(F, keepw, g);
            if (l == g) {
                #pragma unroll
                for (int B = 0; B < 4; B++) {
                    uint32_t mm[8];
                    #pragma unroll
                    for (int j = 0; j < 8; j++) mm[j] = mask[(32 * g + 8 * B + j) * 16 + g];
                    #pragma unroll
                    for (int j = 0; j < 8; j++) {
                        int b = 8 * B + j;
                        if (((kloc >> b) & 1u) && ((vwg >> b) & 1u)) kloc &= ~mm[j];
                    }
                }
            }
            uint32_t alive = __shfl_sync(F, kloc & vwg, g);
            if (l == g) keepw = kloc;
            if (l > g && l < G) {
                uint32_t sup = 0;
                #pragma unroll
                for (int B = 0; B < 4; B++) {
                    uint32_t mm[8];
                    #pragma unroll
                    for (int j = 0; j < 8; j++) mm[j] = mask[(32 * g + 8 * B + j) * 16 + l];
                    #pragma unroll
                    for (int j = 0; j < 8; j++) if ((alive >> (8 * B + j)) & 1u) sup |= mm[j];
                }
                keepw &= ~sup;
            }
        }
        keepw &= validw;
        if (l >= G) keepw = 0;

        uint32_t pc = __popc(keepw);
        uint32_t incl = pc;
        #pragma unroll
        for (int d = 1; d < 32; d <<= 1) {
            uint32_t n = __shfl_up_sync(F, incl, d);
            if (tid >= d) incl += n;
        }
        uint32_t offs  = incl - pc;
        uint32_t total = __shfl_sync(F, incl, G - 1);
        if (l < G) {
            uint32_t slot = offs;
            uint32_t kw = keepw;
            while (kw) {
                int b = __ffs(kw) - 1;
                kw &= kw - 1;
                if (slot < MAXPC) {
                    int gi = bid * MAXPC + (int)slot;
                    int r  = l * 32 + b;
                    g_cls_scores[gi] = ssc[r];
                    g_cls_boxes[gi]  = sxyw[r];
                }
                slot++;
            }
        }
        if (tid == 0) scal[0] = total;
    }
}

// ---------------- kernel 2: fused per (img,class) select + sort + NMS ----------------
__global__ __launch_bounds__(512, 3) void k_main(const float* __restrict__ pred) {
    extern __shared__ char smem[];
    unsigned long long* keys = (unsigned long long*)smem;       // [0,16384)
    uint32_t* hist = (uint32_t*)smem;                           // fallback, [0,32768)
    float4*   sxy  = (float4*)(smem + 16384);
    float4*   sxyw = (float4*)(smem + 24576);
    float*    ssc  = (float*) (smem + 32768);
    float*    sar  = (float*) (smem + 34816);
    uint32_t* mask = (uint32_t*)(smem + 36864);
    uint32_t* sufp = (uint32_t*)(smem + 69632);
    uint32_t* wsum = (uint32_t*)(smem + 71684);
    uint32_t* wsuf = (uint32_t*)(smem + 71748);
    uint32_t* scal = (uint32_t*)(smem + 71812);

    int tid = threadIdx.x;
    int bid = blockIdx.x;                 // img*80 + cls
    int img = bid / N_CLS;
    int cls = bid - img * N_CLS;
    int w = tid >> 5, lane = tid & 31;

    uint32_t cnt = g_cnt[bid];
    int SORTN;

    if (cnt >= PRE && cnt <= 1024) {
        SORTN = 1024;
        const unsigned long long* src = &g_cand[(size_t)bid * CAND_MAX];
        for (int i = tid; i < 1024; i += 512)
            keys[i] = (i < (int)cnt) ? src[i] : 0ull;
        __syncthreads();
    } else if (cnt > 1024 && cnt <= CAND_MAX) {
        SORTN = CAND_MAX;
        const unsigned long long* src = &g_cand[(size_t)bid * CAND_MAX];
        for (int i = tid; i < CAND_MAX; i += 512)
            keys[i] = (i < (int)cnt) ? src[i] : 0ull;
        __syncthreads();
    } else {
        // exact fallback: 8192-bin histogram select over the full column
        SORTN = CAND_MAX;
        for (int i = tid; i < 8192; i += 512) hist[i] = 0;
        __syncthreads();
        for (int a = tid; a < N_ANCH; a += 512) {
            float x = pred[((size_t)img * N_ANCH + a) * 84 + 4 + cls];
            float s = __fdividef(1.0f, 1.0f + __expf(-x));
            uint32_t m = __float_as_uint(s) | 0x80000000u;
            agg_hist_add(hist, m >> 19, true);
        }
        __syncthreads();
        uint32_t v = 0;
        #pragma unroll
        for (int b = 0; b < 16; b++) v += hist[tid * 16 + ((b + tid) & 15)];
        suffix_scan_512(v, sufp, wsum, wsuf, tid);
        {
            uint32_t cur = sufp[tid], nxt = sufp[tid + 1];
            if (cur >= PRE && nxt < PRE) {
                uint32_t run = nxt;
                int T = tid * 16;
                for (int b = 15; b >= 0; b--) {
                    run += hist[tid * 16 + b];
                    if (run >= PRE) { T = tid * 16 + b; break; }
                }
                scal[1] = (uint32_t)T << 19;
            }
            if (tid == 0) scal[3] = 0;
        }
        __syncthreads();
        uint32_t thr = scal[1];
        __syncthreads();
        for (int i = tid; i < CAND_MAX; i += 512) keys[i] = 0ull;
        __syncthreads();
        for (int a = tid; a < N_ANCH; a += 512) {
            float x = pred[((size_t)img * N_ANCH + a) * 84 + 4 + cls];
            float s = __fdividef(1.0f, 1.0f + __expf(-x));
            uint32_t m = __float_as_uint(s) | 0x80000000u;
            if (m >= thr) {
                uint32_t p = atomicAdd(&scal[3], 1u);
                if (p < CAND_MAX)
                    keys[p] = ((unsigned long long)m << 32) | (uint32_t)(~(uint32_t)a);
            }
        }
        __syncthreads();
    }

    bitonic_sort_t<512>(keys, SORTN, tid);

    // gather top-512: load raw box pred, decode here
    {
        unsigned long long key = keys[SORTN - 1 - tid];
        uint32_t a = ~((uint32_t)key);
        if (a >= N_ANCH) a = 0;
        uint32_t m = (uint32_t)(key >> 32);
        float s = __uint_as_float(m ^ 0x80000000u);

        float4 r = ((const float4*)pred)[((size_t)img * N_ANCH + a) * 21];
        float cx, cy, aw, ah;
        anchor_params((int)a, cx, cy, aw, ah);
        float4 b;
        b.x = r.x * 0.1f * aw + cx;
        b.y = r.y * 0.1f * ah + cy;
        b.z = __expf(r.z * 0.2f) * aw;
        b.w = __expf(r.w * 0.2f) * ah;

        float4 e;
        e.x = b.x - b.z * 0.5f; e.y = b.y - b.w * 0.5f;
        e.z = b.x + b.z * 0.5f; e.w = b.y + b.w * 0.5f;
        ssc[tid]  = s;
        sxyw[tid] = b;
        sxy[tid]  = e;
        sar[tid]  = (e.z - e.x) * (e.w - e.y);
    }
    __syncthreads();

    // fast path: 36 tiles covering the top-256 upper triangle
    iou_tiles(sxy, sar, mask, 0, 36, w, lane);
    __syncthreads();
    greedy_emit(ssc, sxyw, mask, scal, 8, bid, tid);
    __syncthreads();

    uint32_t total = scal[0];
    if (total >= MAXD) return;   // exact: top-100 keepers all within top-256

    // fallback (~never): extend to full 512
    iou_tiles(sxy, sar, mask, 36, 136, w, lane);
    __syncthreads();
    greedy_emit(ssc, sxyw, mask, scal, 16, bid, tid);
    __syncthreads();
    total = scal[0];
    if (tid < MAXPC && (uint32_t)tid >= total) {
        int gi = bid * MAXPC + tid;
        g_cls_scores[gi] = -1.0f;
        g_cls_boxes[gi]  = make_float4(-1.0f, -1.0f, -1.0f, -1.0f);
    }
}

// ---------------- kernel 3: per-image merge, 1024 thr, register-staged keys ----------------
__global__ __launch_bounds__(MRG_THREADS) void k_merge(float* __restrict__ out) {
    extern __shared__ char smem[];
    uint32_t* hist = (uint32_t*)smem;                       // 4096 bins
    unsigned long long* keys = (unsigned long long*)smem;   // overlay
    uint32_t* sufp = (uint32_t*)(smem + 16384);             // 1025 u32
    uint32_t* wsum = (uint32_t*)(smem + 20484);
    uint32_t* wsuf = (uint32_t*)(smem + 20612);
    uint32_t* scal = (uint32_t*)(smem + 20740);

    int tid = threadIdx.x;
    int img = blockIdx.x;
    const int TOT = N_CLS * MAXPC;   // 8000
    const int K = 8;

    uint32_t mk[K];
    bool     ok[K];
    #pragma unroll
    for (int k = 0; k < K; k++) {
        int e = tid + k * MRG_THREADS;
        ok[k] = (e < TOT);
        mk[k] = 0;
        if (ok[k]) {
            uint32_t b = __float_as_uint(g_cls_scores[img * TOT + e]);
            mk[k] = (b & 0x80000000u) ? ~b : (b | 0x80000000u);
        }
    }

    for (int i = tid; i < 4096; i += MRG_THREADS) hist[i] = 0;
    __syncthreads();
    #pragma unroll
    for (int k = 0; k < K; k++) agg_hist_add(hist, mk[k] >> 20, ok[k]);
    __syncthreads();

    uint32_t v = 0;
    #pragma unroll
    for (int b = 0; b < 4; b++) v += hist[tid * 4 + ((b + tid) & 3)];
    suffix_scan_1024(v, sufp, wsum, wsuf, tid);

    {
        uint32_t cur = sufp[tid], nxt = sufp[tid + 1];
        if (cur >= MAXD && nxt < MAXD) {
            uint32_t run = nxt;
            int T = tid * 4;
            uint32_t above = nxt;
            for (int b = 3; b >= 0; b--) {
                uint32_t h = hist[tid * 4 + b];
                run += h;
                if (run >= MAXD) { T = tid * 4 + b; above = run - h; break; }
            }
            scal[0] = (uint32_t)T;
            scal[1] = above;
        }
        if (tid == 0) scal[3] = 0;
    }
    __syncthreads();
    uint32_t T1    = scal[0];
    uint32_t above = scal[1];
    uint32_t need  = MAXD - above;

    for (int i = tid; i < 4096; i += MRG_THREADS) hist[i] = 0;
    __syncthreads();
    #pragma unroll
    for (int k = 0; k < K; k++)
        agg_hist_add(hist, (mk[k] >> 8) & 0xFFFu, ok[k] && ((mk[k] >> 20) == T1));
    __syncthreads();

    v = 0;
    #pragma unroll
    for (int b = 0; b < 4; b++) v += hist[tid * 4 + ((b + tid) & 3)];
    suffix_scan_1024(v, sufp, wsum, wsuf, tid);

    {
        uint32_t cur = sufp[tid], nxt = sufp[tid + 1];
        if (cur >= need && nxt < need) {
            uint32_t run = nxt;
            int T = tid * 4;
            for (int b = 3; b >= 0; b--) {
                run += hist[tid * 4 + b];
                if (run >= need) { T = tid * 4 + b; break; }
            }
            scal[2] = (uint32_t)T;
        }
    }
    __syncthreads();
    uint32_t T2 = scal[2];
    __syncthreads();

    for (int i = tid; i < 1024; i += MRG_THREADS) keys[i] = 0ull;
    __syncthreads();
    #pragma unroll
    for (int k = 0; k < K; k++) {
        if (!ok[k]) continue;
        uint32_t b1 = mk[k] >> 20;
        bool cand = (b1 > T1) || (b1 == T1 && ((mk[k] >> 8) & 0xFFFu) >= T2);
        if (cand) {
            int e = tid + k * MRG_THREADS;
            uint32_t p = atomicAdd(&scal[3], 1u);
            if (p < 1024)
                keys[p] = ((unsigned long long)mk[k] << 32) | (uint32_t)(~(uint32_t)e);
        }
    }
    __syncthreads();
    uint32_t C = min(scal[3], 1024u);
    int SORTN = 1024;
    if      (C <= 128) SORTN = 128;
    else if (C <= 256) SORTN = 256;
    else if (C <= 512) SORTN = 512;

    bitonic_sort_t<MRG_THREADS>(keys, SORTN, tid);

    if (tid == 0) scal[1] = 0;
    __syncthreads();
    if (tid < MAXD) {
        unsigned long long key = keys[SORTN - 1 - tid];
        uint32_t e = ~((uint32_t)key);
        float s  = g_cls_scores[img * TOT + e];
        float4 b = g_cls_boxes[img * TOT + e];
        bool valid = (s >= 0.05f);
        int cls = (int)(e / MAXPC);
        int o = img * MAXD + tid;
        float4 ob = valid ? b : make_float4(-1.0f, -1.0f, -1.0f, -1.0f);
        ((float4*)out)[o]  = ob;
        out[1600 + o] = valid ? s : -1.0f;
        out[2000 + o] = valid ? (float)cls : -1.0f;
        if (valid) atomicAdd(&scal[1], 1u);
    }
    __syncthreads();
    if (tid == 0) out[2400 + img] = (float)scal[1];

    // reset this image's candidate counters for the next launch
    if (tid < N_CLS) g_cnt[img * N_CLS + tid] = 0;
}

// ---------------- launcher ----------------
extern "C" void kernel_launch(void* const* d_in, const int* in_sizes, int n_in,
                              void* d_out, int out_size) {
    const float* pred = (const float*)d_in[1];
    if (n_in >= 1 && in_sizes[0] == N_IMG * N_ANCH * 84)
        pred = (const float*)d_in[0];

    cudaFuncSetAttribute(k_main,  cudaFuncAttributeMaxDynamicSharedMemorySize, MAIN_SMEM);
    cudaFuncSetAttribute(k_merge, cudaFuncAttributeMaxDynamicSharedMemorySize, MRG_SMEM);

    const int TOTV = N_IMG * N_ANCH * 21;
    const int PER_BLK = PREP_THREADS * PREP_UNROLL;
    k_prep<<<(TOTV + PER_BLK - 1) / PER_BLK, PREP_THREADS>>>(pred);
    k_main<<<NLIST, 512, MAIN_SMEM>>>(pred);
    k_merge<<<N_IMG, MRG_THREADS, MRG_SMEM>>>((float*)d_out);
}

// round 17
// speedup vs baseline: 1.1117x; 1.1117x over previous
#include <cuda_runtime.h>
#include <cstdint>
#include <math.h>

#define N_IMG   4
#define N_ANCH  76725
#define N_CLS   80
#define PRE     512
#define CAND_MAX 2048
#define MAXPC   100
#define MAXD    100
#define NLIST   (N_IMG * N_CLS)

// logit(0.91): s > 0.91 <=> x > 2.3136168
#define XTHR 2.3136168f

#define MAIN_SMEM 71872
#define MRG_SMEM 20800
#define MRG_THREADS 1024

// ---------------- scratch ----------------
__device__ unsigned long long g_cand[(size_t)NLIST * CAND_MAX];
__device__ uint32_t g_cnt[NLIST];                // zeroed at load; k_merge re-zeros each launch
__device__ float  g_cls_scores[NLIST * MAXPC];
__device__ float4 g_cls_boxes [NLIST * MAXPC];

// decode anchor a -> (cx, cy, aw, ah)
__device__ __forceinline__ void anchor_params(int a, float& cx, float& cy, float& aw, float& ah) {
    int off, fw, stride;
    if      (a < 57600) { off = 0;     fw = 80; stride = 8;   }
    else if (a < 72000) { off = 57600; fw = 40; stride = 16;  }
    else if (a < 75600) { off = 72000; fw = 20; stride = 32;  }
    else if (a < 76500) { off = 75600; fw = 10; stride = 64;  }
    else                { off = 76500; fw = 5;  stride = 128; }
    int rem  = a - off;
    int cell = rem / 9, k = rem - cell * 9;
    int iy = cell / fw, ix = cell - iy * fw;
    float sf    = (float)stride;
    float area  = 16.0f * sf * sf;
    float ratio = (k < 3) ? 0.5f : ((k < 6) ? 1.0f : 2.0f);
    int   si    = k % 3;
    float scale = (si == 0) ? 1.0f : ((si == 1) ? 1.2599210498948732f : 1.5874010519681994f);
    float hh = sqrtf(area / ratio);
    float ww = area / hh;
    cx = (ix + 0.5f) * sf;
    cy = (iy + 0.5f) * sf;
    aw = scale * ww;
    ah = scale * hh;
}

// ---------------- kernel 1: lean logit scan + smem-staged candidate push (R15 form) ----------------
#define PREP_THREADS 512
#define PREP_UNROLL 4
#define PREP_BUF 1024
__global__ __launch_bounds__(PREP_THREADS) void k_prep(const float* __restrict__ pred) {
    __shared__ unsigned long long skey[PREP_BUF];
    __shared__ uint32_t slist[PREP_BUF];
    __shared__ uint32_t scount[NLIST];
    __shared__ uint32_t sbase [NLIST];
    __shared__ uint32_t scursor[NLIST];
    __shared__ uint32_t snum;

    const int TOTV = N_IMG * N_ANCH * 21;
    const int PERIOD = N_ANCH * 21;
    const float4* __restrict__ p4 = (const float4*)pred;
    int tid = threadIdx.x;
    int lane = tid & 31;
    const uint32_t F = 0xFFFFFFFFu;

    if (tid == 0) snum = 0;
    for (int i = tid; i < NLIST; i += PREP_THREADS) { scount[i] = 0; scursor[i] = 0; }
    __syncthreads();

    int base = blockIdx.x * (PREP_THREADS * PREP_UNROLL) + tid;

    float4 v[PREP_UNROLL];
    #pragma unroll
    for (int i = 0; i < PREP_UNROLL; i++) {
        int g = base + i * PREP_THREADS;
        if (g < TOTV) v[i] = p4[g];
    }

    // q = g % 21, maintained incrementally (step 512 % 21 == 8)
    int q = base % 21;

    #pragma unroll
    for (int i = 0; i < PREP_UNROLL; i++) {
        int g = base + i * PREP_THREADS;
        bool inb = (g < TOTV);
        bool isLogit = inb && (q != 0);

        float mx = fmaxf(fmaxf(v[i].x, v[i].y), fmaxf(v[i].z, v[i].w));
        bool any = isLogit && (mx > XTHR);

        if (__ballot_sync(F, any) != 0) {
            int img = g / PERIOD;
            int a   = (g - img * PERIOD) / 21;
            float xs[4] = {v[i].x, v[i].y, v[i].z, v[i].w};
            #pragma unroll
            for (int j = 0; j < 4; j++) {
                bool cand = isLogit && (xs[j] > XTHR);
                uint32_t bmask = __ballot_sync(F, cand);
                if (bmask == 0) continue;
                uint32_t nc = __popc(bmask);
                int ldr = __ffs(bmask) - 1;
                uint32_t wbase = 0;
                if (lane == ldr) wbase = atomicAdd(&snum, nc);
                wbase = __shfl_sync(F, wbase, ldr);
                if (cand) {
                    uint32_t idx = wbase + __popc(bmask & ((1u << lane) - 1u));
                    int cls = 4 * q + j - 4;
                    float s = __fdividef(1.0f, 1.0f + __expf(-xs[j]));
                    uint32_t mono = __float_as_uint(s) | 0x80000000u;
                    uint32_t list = (uint32_t)(img * N_CLS + cls);
                    unsigned long long key =
                        ((unsigned long long)mono << 32) | (uint32_t)(~(uint32_t)a);
                    if (idx < PREP_BUF) {
                        skey[idx]  = key;
                        slist[idx] = list;
                    } else {
                        uint32_t p = atomicAdd(&g_cnt[list], 1u);
                        if (p < CAND_MAX) g_cand[(size_t)list * CAND_MAX + p] = key;
                    }
                }
            }
        }
        q += 8; if (q >= 21) q -= 21;
    }
    __syncthreads();

    int tot = (int)min(snum, (uint32_t)PREP_BUF);

    for (int i = tid; i < tot; i += PREP_THREADS)
        atomicAdd(&scount[slist[i]], 1u);
    __syncthreads();

    for (int l = tid; l < NLIST; l += PREP_THREADS)
        if (scount[l]) sbase[l] = atomicAdd(&g_cnt[l], scount[l]);
    __syncthreads();

    for (int i = tid; i < tot; i += PREP_THREADS) {
        uint32_t l = slist[i];
        uint32_t pos = sbase[l] + atomicAdd(&scursor[l], 1u);
        if (pos < CAND_MAX) g_cand[(size_t)l * CAND_MAX + pos] = skey[i];
    }
}

// suffix scan over 512 threads
__device__ __forceinline__ void suffix_scan_512(uint32_t v, uint32_t* sufp,
                                                uint32_t* wsum, uint32_t* wsuf, int tid) {
    int lane = tid & 31, wid = tid >> 5;
    uint32_t incl = v;
    #pragma unroll
    for (int d = 1; d < 32; d <<= 1) {
        uint32_t n = __shfl_down_sync(0xFFFFFFFFu, incl, d);
        if (lane + d < 32) incl += n;
    }
    if (lane == 0) wsum[wid] = incl;
    __syncthreads();
    if (tid < 16) {
        uint32_t x = wsum[tid];
        #pragma unroll
        for (int d = 1; d < 16; d <<= 1) {
            uint32_t n = __shfl_down_sync(0x0000FFFFu, x, d);
            if (tid + d < 16) x += n;
        }
        wsuf[tid] = x;
    }
    __syncthreads();
    uint32_t below = (wid < 15) ? wsuf[wid + 1] : 0u;
    sufp[tid] = incl + below;
    if (tid == 0) sufp[512] = 0;
    __syncthreads();
}

// suffix scan over 1024 threads (k_merge)
__device__ __forceinline__ void suffix_scan_1024(uint32_t v, uint32_t* sufp,
                                                 uint32_t* wsum, uint32_t* wsuf, int tid) {
    int lane = tid & 31, wid = tid >> 5;
    uint32_t incl = v;
    #pragma unroll
    for (int d = 1; d < 32; d <<= 1) {
        uint32_t n = __shfl_down_sync(0xFFFFFFFFu, incl, d);
        if (lane + d < 32) incl += n;
    }
    if (lane == 0) wsum[wid] = incl;
    __syncthreads();
    if (tid < 32) {
        uint32_t x = wsum[tid];
        #pragma unroll
        for (int d = 1; d < 32; d <<= 1) {
            uint32_t n = __shfl_down_sync(0xFFFFFFFFu, x, d);
            if (tid + d < 32) x += n;
        }
        wsuf[tid] = x;
    }
    __syncthreads();
    uint32_t below = (wid < 31) ? wsuf[wid + 1] : 0u;
    sufp[tid] = incl + below;
    if (tid == 0) sufp[1024] = 0;
    __syncthreads();
}

__device__ __forceinline__ void agg_hist_add(uint32_t* hist, uint32_t bin, bool active) {
    uint32_t amask = __ballot_sync(0xFFFFFFFFu, active);
    if (!active) return;
    uint32_t peers  = __match_any_sync(amask, bin);
    int      leader = __ffs(peers) - 1;
    if ((threadIdx.x & 31) == leader) atomicAdd(&hist[bin], (uint32_t)__popc(peers));
}

// pair-indexed bitonic sort, NT threads (fallback / 2048 path)
template<int NT>
__device__ __forceinline__ void bitonic_sort_t(unsigned long long* keys, int SORTN, int tid) {
    int npairs = SORTN >> 1;
    for (int k = 2; k <= SORTN; k <<= 1) {
        for (int j = k >> 1; j > 0; j >>= 1) {
            for (int p = tid; p < npairs; p += NT) {
                int i = ((p & ~(j - 1)) << 1) | (p & (j - 1));
                int l = i + j;
                unsigned long long x = keys[i], y = keys[l];
                bool up = ((i & k) == 0);
                if (up ? (x > y) : (x < y)) { keys[i] = y; keys[l] = x; }
            }
            __syncthreads();
        }
    }
}

// shfl compare-exchange for bitonic stage (k, j<32) on register r at element index i
__device__ __forceinline__ unsigned long long cmpex_shfl(unsigned long long r,
                                                         int lane, int i, int k, int j) {
    unsigned long long y = __shfl_xor_sync(0xFFFFFFFFu, r, j);
    bool lower = ((lane & j) == 0);
    bool up    = ((i & k) == 0);
    if (lower == up) r = (y < r) ? y : r;   // keep min
    else             r = (y > r) ? y : r;   // keep max
    return r;
}

// hybrid bitonic sort of exactly 1024 keys with 512 threads:
// warp-register segments of 64, smem passes only for j>=64. ~15 barriers vs 55.
__device__ __forceinline__ void hybrid_sort_1024(unsigned long long* keys, int tid) {
    int lane = tid & 31, w = tid >> 5;
    int i0 = w * 64 + lane, i1 = i0 + 32;
    unsigned long long e0 = keys[i0], e1 = keys[i1];

    // intra-warp stages k = 2..32 (pairs stay within each register)
    #pragma unroll
    for (int k = 2; k <= 32; k <<= 1) {
        #pragma unroll
        for (int j = k >> 1; j >= 1; j >>= 1) {
            e0 = cmpex_shfl(e0, lane, i0, k, j);
            e1 = cmpex_shfl(e1, lane, i1, k, j);
        }
    }
    // k = 64: j=32 cross-register swap, then j=16..1 via shfl
    {
        bool up = ((i0 & 64) == 0);
        unsigned long long lo = (e0 < e1) ? e0 : e1;
        unsigned long long hi = (e0 < e1) ? e1 : e0;
        e0 = up ? lo : hi; e1 = up ? hi : lo;
        #pragma unroll
        for (int j = 16; j >= 1; j >>= 1) {
            e0 = cmpex_shfl(e0, lane, i0, 64, j);
            e1 = cmpex_shfl(e1, lane, i1, 64, j);
        }
    }
    keys[i0] = e0; keys[i1] = e1;
    __syncthreads();

    // k = 128..1024: smem passes for j>=64, register finish for j<=32
    for (int k = 128; k <= 1024; k <<= 1) {
        for (int j = k >> 1; j >= 64; j >>= 1) {
            int ii = ((tid & ~(j - 1)) << 1) | (tid & (j - 1));
            int ll = ii + j;
            unsigned long long x = keys[ii], y = keys[ll];
            bool up = ((ii & k) == 0);
            if (up ? (x > y) : (x < y)) { keys[ii] = y; keys[ll] = x; }
            __syncthreads();
        }
        e0 = keys[i0]; e1 = keys[i1];
        bool up = ((i0 & k) == 0);        // uniform across the 64-segment for k>=128
        {
            unsigned long long lo = (e0 < e1) ? e0 : e1;
            unsigned long long hi = (e0 < e1) ? e1 : e0;
            e0 = up ? lo : hi; e1 = up ? hi : lo;
        }
        #pragma unroll
        for (int j = 16; j >= 1; j >>= 1) {
            e0 = cmpex_shfl(e0, lane, i0, k, j);
            e1 = cmpex_shfl(e1, lane, i1, k, j);
        }
        keys[i0] = e0; keys[i1] = e1;
        __syncthreads();
    }
}

// IoU bitmask tiles [t0,t1) striped over 16 warps; mask[row*16+J]
__device__ __forceinline__ void iou_tiles(const float4* sxy, const float* sar,
                                          uint32_t* mask, int t0, int t1,
                                          int w, int lane) {
    for (int t = t0 + w; t < t1; t += 16) {
        int J = 0;
        #pragma unroll
        for (int jj = 1; jj < 16; jj++) if ((jj * (jj + 1)) / 2 <= t) J = jj;
        int I = t - (J * (J + 1)) / 2;

        int col = 32 * J + lane;
        float4 me = sxy[col];
        float  aj = sar[col];
        bool diag = (I == J);

        #pragma unroll 4
        for (int r = 0; r < 32; r++) {
            int row = 32 * I + r;
            float4 bi = sxy[row];
            float lx = fmaxf(bi.x, me.x), ly = fmaxf(bi.y, me.y);
            float rx = fminf(bi.z, me.z), ry = fminf(bi.w, me.w);
            float ww = fmaxf(rx - lx, 0.0f), hh = fmaxf(ry - ly, 0.0f);
            float inter = ww * hh;
            float un = fmaxf(sar[row] + aj - inter, 1e-8f);
            bool bit = (inter > 0.5f * un) && (!diag || (lane > r));
            uint32_t bm = __ballot_sync(0xFFFFFFFFu, bit);
            if (lane == 0) mask[row * 16 + J] = bm;
        }
    }
}

// greedy over G groups; emits keepers; count in scal[0]
__device__ __forceinline__ void greedy_emit(const float* ssc, const float4* sxyw,
                                            const uint32_t* mask, uint32_t* scal,
                                            int G, int bid, int tid) {
    if (tid < 32) {
        const uint32_t F = 0xFFFFFFFFu;
        int l = tid;
        uint32_t validw = 0;
        if (l < G) {
            #pragma unroll
            for (int b = 0; b < 32; b++)
                validw |= (ssc[l * 32 + b] > 0.05f) ? (1u << b) : 0u;
        }
        uint32_t keepw = 0xFFFFFFFFu;
        #pragma unroll 1
        for (int g = 0; g < G; g++) {
            uint32_t vwg  = __shfl_sync(F, validw, g);
            uint32_t kloc = __shfl_sync(F, keepw, g);
            if (l == g) {
                #pragma unroll
                for (int B = 0; B < 4; B++) {
                    uint32_t mm[8];
                    #pragma unroll
                    for (int j = 0; j < 8; j++) mm[j] = mask[(32 * g + 8 * B + j) * 16 + g];
                    #pragma unroll
                    for (int j = 0; j < 8; j++) {
                        int b = 8 * B + j;
                        if (((kloc >> b) & 1u) && ((vwg >> b) & 1u)) kloc &= ~mm[j];
                    }
                }
            }
            uint32_t alive = __shfl_sync(F, kloc & vwg, g);
            if (l == g) keepw = kloc;
            if (l > g && l < G) {
                uint32_t sup = 0;
                #pragma unroll
                for (int B = 0; B < 4; B++) {
                    uint32_t mm[8];
                    #pragma unroll
                    for (int j = 0; j < 8; j++) mm[j] = mask[(32 * g + 8 * B + j) * 16 + l];
                    #pragma unroll
                    for (int j = 0; j < 8; j++) if ((alive >> (8 * B + j)) & 1u) sup |= mm[j];
                }
                keepw &= ~sup;
            }
        }
        keepw &= validw;
        if (l >= G) keepw = 0;

        uint32_t pc = __popc(keepw);
        uint32_t incl = pc;
        #pragma unroll
        for (int d = 1; d < 32; d <<= 1) {
            uint32_t n = __shfl_up_sync(F, incl, d);
            if (tid >= d) incl += n;
        }
        uint32_t offs  = incl - pc;
        uint32_t total = __shfl_sync(F, incl, G - 1);
        if (l < G) {
            uint32_t slot = offs;
            uint32_t kw = keepw;
            while (kw) {
                int b = __ffs(kw) - 1;
                kw &= kw - 1;
                if (slot < MAXPC) {
                    int gi = bid * MAXPC + (int)slot;
                    int r  = l * 32 + b;
                    g_cls_scores[gi] = ssc[r];
                    g_cls_boxes[gi]  = sxyw[r];
                }
                slot++;
            }
        }
        if (tid == 0) scal[0] = total;
    }
}

// ---------------- kernel 2: fused per (img,class) select + sort + NMS ----------------
__global__ __launch_bounds__(512, 3) void k_main(const float* __restrict__ pred) {
    extern __shared__ char smem[];
    unsigned long long* keys = (unsigned long long*)smem;       // [0,16384)
    uint32_t* hist = (uint32_t*)smem;                           // fallback, [0,32768)
    float4*   sxy  = (float4*)(smem + 16384);
    float4*   sxyw = (float4*)(smem + 24576);
    float*    ssc  = (float*) (smem + 32768);
    float*    sar  = (float*) (smem + 34816);
    uint32_t* mask = (uint32_t*)(smem + 36864);
    uint32_t* sufp = (uint32_t*)(smem + 69632);
    uint32_t* wsum = (uint32_t*)(smem + 71684);
    uint32_t* wsuf = (uint32_t*)(smem + 71748);
    uint32_t* scal = (uint32_t*)(smem + 71812);

    int tid = threadIdx.x;
    int bid = blockIdx.x;                 // img*80 + cls
    int img = bid / N_CLS;
    int cls = bid - img * N_CLS;
    int w = tid >> 5, lane = tid & 31;

    uint32_t cnt = g_cnt[bid];
    int SORTN;

    if (cnt >= PRE && cnt <= 1024) {
        SORTN = 1024;
        const unsigned long long* src = &g_cand[(size_t)bid * CAND_MAX];
        for (int i = tid; i < 1024; i += 512)
            keys[i] = (i < (int)cnt) ? src[i] : 0ull;
        __syncthreads();
    } else if (cnt > 1024 && cnt <= CAND_MAX) {
        SORTN = CAND_MAX;
        const unsigned long long* src = &g_cand[(size_t)bid * CAND_MAX];
        for (int i = tid; i < CAND_MAX; i += 512)
            keys[i] = (i < (int)cnt) ? src[i] : 0ull;
        __syncthreads();
    } else {
        // exact fallback: 8192-bin histogram select over the full column
        SORTN = CAND_MAX;
        for (int i = tid; i < 8192; i += 512) hist[i] = 0;
        __syncthreads();
        for (int a = tid; a < N_ANCH; a += 512) {
            float x = pred[((size_t)img * N_ANCH + a) * 84 + 4 + cls];
            float s = __fdividef(1.0f, 1.0f + __expf(-x));
            uint32_t m = __float_as_uint(s) | 0x80000000u;
            agg_hist_add(hist, m >> 19, true);
        }
        __syncthreads();
        uint32_t v = 0;
        #pragma unroll
        for (int b = 0; b < 16; b++) v += hist[tid * 16 + ((b + tid) & 15)];
        suffix_scan_512(v, sufp, wsum, wsuf, tid);
        {
            uint32_t cur = sufp[tid], nxt = sufp[tid + 1];
            if (cur >= PRE && nxt < PRE) {
                uint32_t run = nxt;
                int T = tid * 16;
                for (int b = 15; b >= 0; b--) {
                    run += hist[tid * 16 + b];
                    if (run >= PRE) { T = tid * 16 + b; break; }
                }
                scal[1] = (uint32_t)T << 19;
            }
            if (tid == 0) scal[3] = 0;
        }
        __syncthreads();
        uint32_t thr = scal[1];
        __syncthreads();
        for (int i = tid; i < CAND_MAX; i += 512) keys[i] = 0ull;
        __syncthreads();
        for (int a = tid; a < N_ANCH; a += 512) {
            float x = pred[((size_t)img * N_ANCH + a) * 84 + 4 + cls];
            float s = __fdividef(1.0f, 1.0f + __expf(-x));
            uint32_t m = __float_as_uint(s) | 0x80000000u;
            if (m >= thr) {
                uint32_t p = atomicAdd(&scal[3], 1u);
                if (p < CAND_MAX)
                    keys[p] = ((unsigned long long)m << 32) | (uint32_t)(~(uint32_t)a);
            }
        }
        __syncthreads();
    }

    if (SORTN == 1024) hybrid_sort_1024(keys, tid);
    else               bitonic_sort_t<512>(keys, SORTN, tid);

    // gather top-512: load raw box pred, decode here
    {
        unsigned long long key = keys[SORTN - 1 - tid];
        uint32_t a = ~((uint32_t)key);
        if (a >= N_ANCH) a = 0;
        uint32_t m = (uint32_t)(key >> 32);
        float s = __uint_as_float(m ^ 0x80000000u);

        float4 r = ((const float4*)pred)[((size_t)img * N_ANCH + a) * 21];
        float cx, cy, aw, ah;
        anchor_params((int)a, cx, cy, aw, ah);
        float4 b;
        b.x = r.x * 0.1f * aw + cx;
        b.y = r.y * 0.1f * ah + cy;
        b.z = __expf(r.z * 0.2f) * aw;
        b.w = __expf(r.w * 0.2f) * ah;

        float4 e;
        e.x = b.x - b.z * 0.5f; e.y = b.y - b.w * 0.5f;
        e.z = b.x + b.z * 0.5f; e.w = b.y + b.w * 0.5f;
        ssc[tid]  = s;
        sxyw[tid] = b;
        sxy[tid]  = e;
        sar[tid]  = (e.z - e.x) * (e.w - e.y);
    }
    __syncthreads();

    // fast path: 36 tiles covering the top-256 upper triangle
    iou_tiles(sxy, sar, mask, 0, 36, w, lane);
    __syncthreads();
    greedy_emit(ssc, sxyw, mask, scal, 8, bid, tid);
    __syncthreads();

    uint32_t total = scal[0];
    if (total >= MAXD) return;   // exact: top-100 keepers all within top-256

    // fallback (~never): extend to full 512
    iou_tiles(sxy, sar, mask, 36, 136, w, lane);
    __syncthreads();
    greedy_emit(ssc, sxyw, mask, scal, 16, bid, tid);
    __syncthreads();
    total = scal[0];
    if (tid < MAXPC && (uint32_t)tid >= total) {
        int gi = bid * MAXPC + tid;
        g_cls_scores[gi] = -1.0f;
        g_cls_boxes[gi]  = make_float4(-1.0f, -1.0f, -1.0f, -1.0f);
    }
}

// ---------------- kernel 3: per-image merge, rank-by-counting (no sort) ----------------
__global__ __launch_bounds__(MRG_THREADS) void k_merge(float* __restrict__ out) {
    extern __shared__ char smem[];
    uint32_t* hist = (uint32_t*)smem;                       // 4096 bins
    unsigned long long* keys = (unsigned long long*)smem;   // overlay
    uint32_t* sufp = (uint32_t*)(smem + 16384);             // 1025 u32
    uint32_t* wsum = (uint32_t*)(smem + 20484);
    uint32_t* wsuf = (uint32_t*)(smem + 20612);
    uint32_t* scal = (uint32_t*)(smem + 20740);

    int tid = threadIdx.x;
    int img = blockIdx.x;
    const int TOT = N_CLS * MAXPC;   // 8000
    const int K = 8;

    uint32_t mk[K];
    bool     ok[K];
    #pragma unroll
    for (int k = 0; k < K; k++) {
        int e = tid + k * MRG_THREADS;
        ok[k] = (e < TOT);
        mk[k] = 0;
        if (ok[k]) {
            uint32_t b = __float_as_uint(g_cls_scores[img * TOT + e]);
            mk[k] = (b & 0x80000000u) ? ~b : (b | 0x80000000u);
        }
    }

    for (int i = tid; i < 4096; i += MRG_THREADS) hist[i] = 0;
    __syncthreads();
    #pragma unroll
    for (int k = 0; k < K; k++) agg_hist_add(hist, mk[k] >> 20, ok[k]);
    __syncthreads();

    uint32_t v = 0;
    #pragma unroll
    for (int b = 0; b < 4; b++) v += hist[tid * 4 + ((b + tid) & 3)];
    suffix_scan_1024(v, sufp, wsum, wsuf, tid);

    {
        uint32_t cur = sufp[tid], nxt = sufp[tid + 1];
        if (cur >= MAXD && nxt < MAXD) {
            uint32_t run = nxt;
            int T = tid * 4;
            uint32_t above = nxt;
            for (int b = 3; b >= 0; b--) {
                uint32_t h = hist[tid * 4 + b];
                run += h;
                if (run >= MAXD) { T = tid * 4 + b; above = run - h; break; }
            }
            scal[0] = (uint32_t)T;
            scal[1] = above;
        }
        if (tid == 0) scal[3] = 0;
    }
    __syncthreads();
    uint32_t T1    = scal[0];
    uint32_t above = scal[1];
    uint32_t need  = MAXD - above;

    for (int i = tid; i < 4096; i += MRG_THREADS) hist[i] = 0;
    __syncthreads();
    #pragma unroll
    for (int k = 0; k < K; k++)
        agg_hist_add(hist, (mk[k] >> 8) & 0xFFFu, ok[k] && ((mk[k] >> 20) == T1));
    __syncthreads();

    v = 0;
    #pragma unroll
    for (int b = 0; b < 4; b++) v += hist[tid * 4 + ((b + tid) & 3)];
    suffix_scan_1024(v, sufp, wsum, wsuf, tid);

    {
        uint32_t cur = sufp[tid], nxt = sufp[tid + 1];
        if (cur >= need && nxt < need) {
            uint32_t run = nxt;
            int T = tid * 4;
            for (int b = 3; b >= 0; b--) {
                run += hist[tid * 4 + b];
                if (run >= need) { T = tid * 4 + b; break; }
            }
            scal[2] = (uint32_t)T;
        }
    }
    __syncthreads();
    uint32_t T2 = scal[2];
    __syncthreads();   // hist region about to be overwritten by keys

    // compaction (keys overlays hist)
    #pragma unroll
    for (int k = 0; k < K; k++) {
        if (!ok[k]) continue;
        uint32_t b1 = mk[k] >> 20;
        bool cand = (b1 > T1) || (b1 == T1 && ((mk[k] >> 8) & 0xFFFu) >= T2);
        if (cand) {
            int e = tid + k * MRG_THREADS;
            uint32_t p = atomicAdd(&scal[3], 1u);
            if (p < 1024)
                keys[p] = ((unsigned long long)mk[k] << 32) | (uint32_t)(~(uint32_t)e);
        }
    }
    __syncthreads();
    int C = (int)min(scal[3], 1024u);    // C >= MAXD by construction

    if (tid == 0) scal[1] = 0;
    __syncthreads();

    // rank-by-counting: candidate with rank r (r = #{keys greater}) -> output slot r
    for (int i = tid; i < C; i += MRG_THREADS) {
        unsigned long long me = keys[i];
        int rank = 0;
        for (int j = 0; j < C; j++) rank += (keys[j] > me) ? 1 : 0;
        if (rank < MAXD) {
            uint32_t e = ~((uint32_t)me);
            float s  = g_cls_scores[img * TOT + e];
            float4 b = g_cls_boxes[img * TOT + e];
            bool valid = (s >= 0.05f);
            int cls = (int)(e / MAXPC);
            int o = img * MAXD + rank;
            float4 ob = valid ? b : make_float4(-1.0f, -1.0f, -1.0f, -1.0f);
            ((float4*)out)[o]  = ob;
            out[1600 + o] = valid ? s : -1.0f;
            out[2000 + o] = valid ? (float)cls : -1.0f;
            if (valid) atomicAdd(&scal[1], 1u);
        }
    }
    __syncthreads();
    if (tid == 0) out[2400 + img] = (float)scal[1];

    // reset this image's candidate counters for the next launch
    if (tid < N_CLS) g_cnt[img * N_CLS + tid] = 0;
}

// ---------------- launcher ----------------
extern "C" void kernel_launch(void* const* d_in, const int* in_sizes, int n_in,
                              void* d_out, int out_size) {
    const float* pred = (const float*)d_in[1];
    if (n_in >= 1 && in_sizes[0] == N_IMG * N_ANCH * 84)
        pred = (const float*)d_in[0];

    cudaFuncSetAttribute(k_main,  cudaFuncAttributeMaxDynamicSharedMemorySize, MAIN_SMEM);
    cudaFuncSetAttribute(k_merge, cudaFuncAttributeMaxDynamicSharedMemorySize, MRG_SMEM);

    const int TOTV = N_IMG * N_ANCH * 21;
    const int PER_BLK = PREP_THREADS * PREP_UNROLL;
    k_prep<<<(TOTV + PER_BLK - 1) / PER_BLK, PREP_THREADS>>>(pred);
    k_main<<<NLIST, 512, MAIN_SMEM>>>(pred);
    k_merge<<<N_IMG, MRG_THREADS, MRG_SMEM>>>((float*)d_out);
}